// round 16
// baseline (speedup 1.0000x reference)
#include <cuda_runtime.h>
#include <cuda_fp16.h>
#include <cstdint>

#define B_     32
#define CIN    256
#define COUT   256
#define Hs     56
#define Ws     56
#define HW     3136
#define Kdim   2304
#define KZERO  128
#define NIMG   36
#define BTILE  32768
#define SLAB64 3720          /* 58 rows x 64 + pad (16B mult) */
#define TPB    28
#define NTILE  (B_*TPB)

// ---------------- device scratch ----------------
__device__ float d_s[B_*CIN];
__device__ float d_t[B_*COUT];
__device__ __align__(16) __half d_xp[(size_t)B_*CIN*SLAB64];  // x[rr-1][j-1]
__device__ __align__(16) __half d_xq[(size_t)B_*CIN*SLAB64];  // x[rr-1][j]
__device__ __align__(16) __half d_xr[(size_t)B_*CIN*SLAB64];  // x[rr-1][j+1]
__device__ __align__(16) __half d_bimg[(size_t)NIMG*256*64];
__device__ unsigned int d_ctr[2];

// ---------------------------------------------------------------------------
// P0: smem-staged padded fp16 slabs (3 shifts), vectorized I/O + abs-mean
// ---------------------------------------------------------------------------
__global__ void prep_x_kernel(const float* __restrict__ x) {
    __shared__ __align__(16) __half Spad[2 + 58*64 + 8];
    __half* S = Spad + 2;
    int bc = blockIdx.x;
    int t = threadIdx.x;
    const float4* xs4 = (const float4*)(x + (size_t)bc * HW);

    for (int i = t; i < (2 + 58*64 + 8)/2; i += 256)
        ((uint32_t*)Spad)[i] = 0;
    __syncthreads();

    float sum = 0.f;
    for (int j4 = t; j4 < 784; j4 += 256) {
        float4 v = xs4[j4];
        int hy = j4 / 14;
        int wx = (j4 - hy*14) * 4;
        sum += fabsf(v.x) + fabsf(v.y) + fabsf(v.z) + fabsf(v.w);
        __half2* p = (__half2*)(S + (hy+1)*64 + wx);
        p[0] = __halves2half2(__float2half(v.x), __float2half(v.y));
        p[1] = __halves2half2(__float2half(v.z), __float2half(v.w));
    }
    __syncthreads();

    __half* q  = d_xq + (size_t)bc * SLAB64;
    __half* pl = d_xp + (size_t)bc * SLAB64;
    __half* pr = d_xr + (size_t)bc * SLAB64;
    for (int i = t; i < 464; i += 256) {
        const uint32_t* w = (const uint32_t*)(S + i*8 - 2);
        uint32_t B0 = w[0], B1 = w[1], B2 = w[2], B3 = w[3], B4 = w[4], B5 = w[5];
        ((uint4*)q)[i] = make_uint4(B1, B2, B3, B4);
        uint32_t p0 = (B0 >> 16) | (B1 << 16);
        uint32_t p1 = (B1 >> 16) | (B2 << 16);
        uint32_t p2 = (B2 >> 16) | (B3 << 16);
        uint32_t p3 = (B3 >> 16) | (B4 << 16);
        uint32_t p4 = (B4 >> 16) | (B5 << 16);
        ((uint4*)pl)[i] = make_uint4(p0, p1, p2, p3);
        ((uint4*)pr)[i] = make_uint4(p1, p2, p3, p4);
    }

    __shared__ float red[256];
    red[t] = sum;
    __syncthreads();
    for (int s = 128; s > 0; s >>= 1) {
        if (t < s) red[t] += red[t + s];
        __syncthreads();
    }
    if (t == 0) d_s[bc] = red[0] * (1.0f / HW);
}

// ---------------------------------------------------------------------------
// P1: merged gate + pre-swizzled B images (rs-major k order)
// ---------------------------------------------------------------------------
__global__ void gate_w_kernel(const float* __restrict__ gw,
                              const float* __restrict__ gb,
                              const float* __restrict__ cw) {
    int blk = blockIdx.x;
    int c = threadIdx.x;
    if (blk >= B_) {
        int img = blk - B_;
        int rs = img >> 2, cbk = img & 3;
        char* dst = (char*)d_bimg + (size_t)img * BTILE;
        const float* wr = cw + (size_t)c * Kdim;
        for (int kk = 0; kk < 64; kk++) {
            float v = wr[(cbk*64 + kk)*9 + rs];
            uint32_t off = (uint32_t)(c*128 + kk*2);
            off ^= (off >> 3) & 0x70;
            *(__half*)(dst + off) = __float2half(v);
        }
        return;
    }
    int b = blk;
    if (b == 0 && c < 2) d_ctr[c] = 0;
    __shared__ float s_sh[CIN];
    __shared__ float g_sh[COUT];
    __shared__ float red[256];

    s_sh[c] = d_s[b*CIN + c];
    __syncthreads();

    const float* wrow = gw + (size_t)c * CIN;
    float acc = gb[c];
    #pragma unroll 8
    for (int j = 0; j < CIN; j++) acc = fmaf(s_sh[j], wrow[j], acc);
    float g = fmaxf(acc, 0.f);
    g_sh[c] = g;
    __syncthreads();

    int rank = 0;
    for (int j = 0; j < COUT; j++) {
        float gj = g_sh[j];
        rank += (gj < g) || (gj == g && j < c);
    }
    float t = (rank < KZERO) ? 0.f : g;

    red[c] = t;
    __syncthreads();
    for (int s = 128; s > 0; s >>= 1) {
        if (c < s) red[c] += red[c + s];
        __syncthreads();
    }
    d_t[b*COUT + c] = t * ((float)COUT / red[0]);
}

// ---------------------------------------------------------------------------
// Main: persistent fp16 implicit GEMM; uniform cp16 A loads (3 slabs).
// ---------------------------------------------------------------------------
#define SM_A    0
#define SM_B    49152
#define SM_INV  98304
#define SM_ADD  99328
#define SM_TILE 100352
#define SMEM_SZ 100384

__device__ __forceinline__ uint32_t smem_u32(const void* p) {
    uint32_t a;
    asm("{ .reg .u64 t; cvta.to.shared.u64 t, %1; cvt.u32.u64 %0, t; }" : "=r"(a) : "l"(p));
    return a;
}
__device__ __forceinline__ void ldmx4(uint32_t* r, uint32_t addr) {
    asm volatile("ldmatrix.sync.aligned.m8n8.x4.shared.b16 {%0,%1,%2,%3}, [%4];"
        : "=r"(r[0]), "=r"(r[1]), "=r"(r[2]), "=r"(r[3]) : "r"(addr));
}
__device__ __forceinline__ void ldmx4t(uint32_t* r, uint32_t addr) {
    asm volatile("ldmatrix.sync.aligned.m8n8.x4.trans.shared.b16 {%0,%1,%2,%3}, [%4];"
        : "=r"(r[0]), "=r"(r[1]), "=r"(r[2]), "=r"(r[3]) : "r"(addr));
}
__device__ __forceinline__ void mma16816(float* c, const uint32_t* a, const uint32_t* b) {
    asm volatile(
        "mma.sync.aligned.m16n8k16.row.col.f32.f16.f16.f32 "
        "{%0,%1,%2,%3}, {%4,%5,%6,%7}, {%8,%9}, {%0,%1,%2,%3};"
        : "+f"(c[0]), "+f"(c[1]), "+f"(c[2]), "+f"(c[3])
        : "r"(a[0]), "r"(a[1]), "r"(a[2]), "r"(a[3]), "r"(b[0]), "r"(b[1]));
}
__device__ __forceinline__ uint32_t sw128(uint32_t off) {
    return off ^ ((off >> 3) & 0x70);
}
__device__ __forceinline__ uint32_t swzA(uint32_t off) {
    return off ^ (((off >> 8) & 7) << 4);
}
__device__ __forceinline__ void cp16(uint32_t saddr, const void* g) {
    asm volatile("cp.async.cg.shared.global [%0], [%1], 16;" :: "r"(saddr), "l"(g) : "memory");
}
#define CP_COMMIT() asm volatile("cp.async.commit_group;" ::: "memory")
#define CP_WAIT1()  asm volatile("cp.async.wait_group 1;" ::: "memory")
#define CP_WAIT0()  asm volatile("cp.async.wait_group 0;" ::: "memory")

__device__ __forceinline__ void issueA(uint32_t su, int t, unsigned tileid,
                                       int cc, int stg) {
    int rs = cc >> 2, cb = cc & 3;
    int dh = rs / 3, dw = rs - dh*3;
    int bb = (int)(tileid / TPB);
    int tl = (int)(tileid - bb*TPB);
    const __half* base = (dw == 0) ? d_xp : ((dw == 1) ? d_xq : d_xr);
    int rowhalf = tl*128 + dh*64;
    const char* src0 = (const char*)(base + ((size_t)bb*CIN + cb*64) * SLAB64)
                       + (size_t)rowhalf * 2;
    uint32_t dstA = su + SM_A + stg*16384;
    #pragma unroll
    for (int q = 0; q < 4; q++) {
        int u = q*256 + t;
        int ci = u >> 4, s = u & 15;
        cp16(dstA + swzA((uint32_t)(ci*256 + s*16)),
             src0 + (size_t)ci*(SLAB64*2) + s*16);
    }
}

__global__ void __launch_bounds__(256, 2)
conv_mma_kernel(const float* __restrict__ gamma, const float* __restrict__ beta,
                const float* __restrict__ mean,  const float* __restrict__ var,
                float* __restrict__ out)
{
    extern __shared__ __align__(1024) char smem[];
    float* inv_s = (float*)(smem + SM_INV);
    float* add_s = (float*)(smem + SM_ADD);
    volatile unsigned int* tile_s = (volatile unsigned int*)(smem + SM_TILE);
    const uint32_t su = smem_u32(smem);

    const int t = threadIdx.x;
    const int lane = t & 31;
    const int wrp = t >> 5;
    const int wm = (wrp & 1) * 64;
    const int wn = (wrp >> 1) * 32;
    const int nh = blockIdx.x & 1;

    {
        float iv = gamma[t] * rsqrtf(var[t] + 1e-5f);
        inv_s[t] = iv;
        add_s[t] = beta[t] - mean[t]*iv;
    }

    const int a_i  = lane & 7;
    const int a_kh = (lane >> 4) & 1;
    const int a_m8 = ((lane >> 3) & 1) * 8;
    const int b_row = ((lane & 16) ? 8 : 0) + (lane & 7);
    const int b_kb  = (lane & 8) ? 16 : 0;

    const char* bsrc = (const char*)d_bimg + (size_t)nh * 16384;

    if (t == 0) tile_s[0] = atomicAdd(&d_ctr[nh], 1u);
    __syncthreads();
    unsigned tile = tile_s[0];

    if (tile < NTILE) {
        #pragma unroll
        for (int pc = 0; pc < 2; pc++) {
            const char* bs = bsrc + (size_t)pc * BTILE;
            uint32_t bdst = su + SM_B + pc*16384;
            #pragma unroll
            for (int q = 0; q < 4; q++)
                cp16(bdst + (uint32_t)(q*256 + t)*16, bs + (q*256 + t)*16);
            issueA(su, t, tile, pc, pc);
            CP_COMMIT();
        }
        CP_WAIT1();
        __syncthreads();

        for (;;) {
            const int bb = (int)(tile / TPB);
            const int tl = (int)(tile - bb*TPB);

            float acc[4][4][4];
            #pragma unroll
            for (int i = 0; i < 4; i++)
                #pragma unroll
                for (int j = 0; j < 4; j++)
                    #pragma unroll
                    for (int q = 0; q < 4; q++) acc[i][j][q] = 0.f;

            uint32_t afb[2][4][4];
            uint32_t bfb[2][4][2];

            for (int c = 0; c < NIMG; c++) {
                if (c == 0 && t == 0) tile_s[1] = atomicAdd(&d_ctr[nh], 1u);

                const int cc = c + 2;
                const int stg = cc % 3;
                {
                    int bcch = (cc >= NIMG) ? cc - NIMG : cc;
                    const char* bs = bsrc + (size_t)bcch * BTILE;
                    uint32_t bdst = su + SM_B + stg*16384;
                    #pragma unroll
                    for (int q = 0; q < 4; q++)
                        cp16(bdst + (uint32_t)(q*256 + t)*16, bs + (q*256 + t)*16);
                }
                if (cc < NIMG) {
                    issueA(su, t, tile, cc, stg);
                } else {
                    unsigned nt = tile_s[1];
                    if (nt < NTILE) issueA(su, t, nt, cc - NIMG, stg);
                }
                CP_COMMIT();

                const uint32_t Ast = su + SM_A + (c % 3)*16384;
                const uint32_t Bst = su + SM_B + (c % 3)*16384;

                #pragma unroll
                for (int am = 0; am < 4; am++) {
                    uint32_t ad = (uint32_t)((a_kh*8 + a_i)*256
                                           + (wm + am*16 + a_m8)*2);
                    ldmx4t(afb[0][am], Ast + swzA(ad));
                }
                #pragma unroll
                for (int bp = 0; bp < 2; bp++) {
                    uint32_t rr[4];
                    uint32_t off = (uint32_t)((wn + bp*16 + b_row)*128 + b_kb);
                    ldmx4(rr, Bst + sw128(off));
                    bfb[0][2*bp][0] = rr[0]; bfb[0][2*bp][1] = rr[1];
                    bfb[0][2*bp+1][0] = rr[2]; bfb[0][2*bp+1][1] = rr[3];
                }

                #pragma unroll
                for (int ks = 0; ks < 4; ks++) {
                    const int cur = ks & 1;
                    const int nxt = cur ^ 1;
                    if (ks < 3) {
                        #pragma unroll
                        for (int am = 0; am < 4; am++) {
                            uint32_t ad = (uint32_t)(((ks+1)*16 + a_kh*8 + a_i)*256
                                                   + (wm + am*16 + a_m8)*2);
                            ldmx4t(afb[nxt][am], Ast + swzA(ad));
                        }
                        #pragma unroll
                        for (int bp = 0; bp < 2; bp++) {
                            uint32_t rr[4];
                            uint32_t off = (uint32_t)((wn + bp*16 + b_row)*128
                                                    + (ks+1)*32 + b_kb);
                            ldmx4(rr, Bst + sw128(off));
                            bfb[nxt][2*bp][0] = rr[0]; bfb[nxt][2*bp][1] = rr[1];
                            bfb[nxt][2*bp+1][0] = rr[2]; bfb[nxt][2*bp+1][1] = rr[3];
                        }
                    }
                    #pragma unroll
                    for (int am = 0; am < 4; am++)
                        #pragma unroll
                        for (int bn = 0; bn < 4; bn++)
                            mma16816(acc[am][bn], afb[cur][am], bfb[cur][bn]);
                }

                CP_WAIT1();
                __syncthreads();
            }

            const float* tp = d_t + bb*COUT;
            #pragma unroll
            for (int am = 0; am < 4; am++) {
                int mr0 = tl*128 + wm + am*16 + (lane >> 2);
                #pragma unroll
                for (int half = 0; half < 2; half++) {
                    int mp = mr0 + half*8;
                    int h = mp >> 6;
                    int w = mp & 63;
                    bool valid = (w < Ws);
                    float* op = out + (size_t)bb*(COUT*HW) + h*Ws + w;
                    #pragma unroll
                    for (int bn = 0; bn < 4; bn++) {
                        int n = nh*128 + wn + bn*8 + 2*(lane & 3);
                        float v0 = fmaf(acc[am][bn][half*2+0], inv_s[n],   add_s[n]);
                        float v1 = fmaf(acc[am][bn][half*2+1], inv_s[n+1], add_s[n+1]);
                        v0 = fmaxf(v0, 0.f) * __ldg(tp + n);
                        v1 = fmaxf(v1, 0.f) * __ldg(tp + n + 1);
                        if (valid) {
                            op[(size_t)n * HW] = v0;
                            op[(size_t)(n+1) * HW] = v1;
                        }
                    }
                }
            }

            unsigned nt = tile_s[1];
            __syncthreads();
            tile = nt;
            if (tile >= NTILE) break;
        }
    }
    CP_WAIT0();
}

// ---------------------------------------------------------------------------
extern "C" void kernel_launch(void* const* d_in, const int* in_sizes, int n_in,
                              void* d_out, int out_size) {
    const float* x     = (const float*)d_in[0];
    const float* cw    = (const float*)d_in[1];
    const float* gw    = (const float*)d_in[2];
    const float* gb    = (const float*)d_in[3];
    const float* gamma = (const float*)d_in[4];
    const float* beta  = (const float*)d_in[5];
    const float* mean  = (const float*)d_in[6];
    const float* var   = (const float*)d_in[7];
    float* out = (float*)d_out;

    static bool attr_set = false;
    if (!attr_set) {
        cudaFuncSetAttribute(conv_mma_kernel,
                             cudaFuncAttributeMaxDynamicSharedMemorySize, SMEM_SZ);
        attr_set = true;
    }

    prep_x_kernel<<<B_*CIN, 256>>>(x);
    gate_w_kernel<<<B_ + NIMG, 256>>>(gw, gb, cw);
    conv_mma_kernel<<<296, 256, SMEM_SZ>>>(gamma, beta, mean, var, out);
}

// round 17
// speedup vs baseline: 1.0357x; 1.0357x over previous
#include <cuda_runtime.h>
#include <cuda_fp16.h>
#include <cstdint>

#define B_     32
#define CIN    256
#define COUT   256
#define Hs     56
#define Ws     56
#define HW     3136
#define Kdim   2304
#define KZERO  128
#define NIMG   36
#define BTILE  32768
#define SLAB64 3720          /* 58 rows x 64 + pad (16B mult) */
#define TPB    28
#define NTILE  (B_*TPB)

// ---------------- device scratch ----------------
__device__ float d_s[B_*CIN];
__device__ float d_t[B_*COUT];
__device__ __align__(16) __half d_xp[(size_t)B_*CIN*SLAB64];  // x[rr-1][j-1]
__device__ __align__(16) __half d_xq[(size_t)B_*CIN*SLAB64];  // x[rr-1][j]
__device__ __align__(16) __half d_bimg[(size_t)NIMG*256*64];
__device__ unsigned int d_ctr[2];

// ---------------------------------------------------------------------------
// P0: padded fp16 slabs; aligned uint4 writeback + shfl-based 1-half shift
// ---------------------------------------------------------------------------
__global__ void prep_x_kernel(const float* __restrict__ x) {
    __shared__ __align__(16) __half Spad[8 + 58*64 + 8];
    __half* S = Spad + 8;                       // 16B-aligned
    int bc = blockIdx.x;
    int t = threadIdx.x;
    int lane = t & 31;
    const float4* xs4 = (const float4*)(x + (size_t)bc * HW);

    for (int i = t; i < (8 + 58*64 + 8)/2; i += 256)
        ((uint32_t*)Spad)[i] = 0;
    __syncthreads();

    float sum = 0.f;
    for (int j4 = t; j4 < 784; j4 += 256) {
        float4 v = xs4[j4];
        int hy = j4 / 14;
        int wx = (j4 - hy*14) * 4;
        sum += fabsf(v.x) + fabsf(v.y) + fabsf(v.z) + fabsf(v.w);
        __half2* p = (__half2*)(S + (hy+1)*64 + wx);
        p[0] = __halves2half2(__float2half(v.x), __float2half(v.y));
        p[1] = __halves2half2(__float2half(v.z), __float2half(v.w));
    }
    __syncthreads();

    __half* q  = d_xq + (size_t)bc * SLAB64;
    __half* pl = d_xp + (size_t)bc * SLAB64;
    #pragma unroll
    for (int it = 0; it < 2; it++) {
        int i = it*256 + t;
        bool act = (i < 464);
        int ii = act ? i : 463;
        uint4 vq = ((const uint4*)S)[ii];                      // aligned LDS.128
        uint32_t prevw = __shfl_up_sync(0xFFFFFFFFu, vq.w, 1); // lane-1's word 4i-1... wait: lane-1 holds ii-1 -> word 4(ii)-1? yes: its vq.w = word 4(ii-1)+3 = 4*ii-1
        if (lane == 0)
            prevw = ((const uint32_t*)S)[ii*4 - 1];            // S[-..] covered by front pad
        if (act) {
            ((uint4*)q)[i] = vq;
            uint4 vp;
            vp.x = (prevw >> 16) | (vq.x << 16);
            vp.y = (vq.x  >> 16) | (vq.y << 16);
            vp.z = (vq.y  >> 16) | (vq.z << 16);
            vp.w = (vq.z  >> 16) | (vq.w << 16);
            ((uint4*)pl)[i] = vp;
        }
    }

    __shared__ float red[256];
    red[t] = sum;
    __syncthreads();
    for (int s = 128; s > 0; s >>= 1) {
        if (t < s) red[t] += red[t + s];
        __syncthreads();
    }
    if (t == 0) d_s[bc] = red[0] * (1.0f / HW);
}

// ---------------------------------------------------------------------------
// P1: merged gate + pre-swizzled B images (rs-major k order)
// ---------------------------------------------------------------------------
__global__ void gate_w_kernel(const float* __restrict__ gw,
                              const float* __restrict__ gb,
                              const float* __restrict__ cw) {
    int blk = blockIdx.x;
    int c = threadIdx.x;
    if (blk >= B_) {
        int img = blk - B_;
        int rs = img >> 2, cbk = img & 3;
        char* dst = (char*)d_bimg + (size_t)img * BTILE;
        const float* wr = cw + (size_t)c * Kdim;
        for (int kk = 0; kk < 64; kk++) {
            float v = wr[(cbk*64 + kk)*9 + rs];
            uint32_t off = (uint32_t)(c*128 + kk*2);
            off ^= (off >> 3) & 0x70;
            *(__half*)(dst + off) = __float2half(v);
        }
        return;
    }
    int b = blk;
    if (b == 0 && c < 2) d_ctr[c] = 0;
    __shared__ float s_sh[CIN];
    __shared__ float g_sh[COUT];
    __shared__ float red[256];

    s_sh[c] = d_s[b*CIN + c];
    __syncthreads();

    const float* wrow = gw + (size_t)c * CIN;
    float acc = gb[c];
    #pragma unroll 8
    for (int j = 0; j < CIN; j++) acc = fmaf(s_sh[j], wrow[j], acc);
    float g = fmaxf(acc, 0.f);
    g_sh[c] = g;
    __syncthreads();

    int rank = 0;
    for (int j = 0; j < COUT; j++) {
        float gj = g_sh[j];
        rank += (gj < g) || (gj == g && j < c);
    }
    float t = (rank < KZERO) ? 0.f : g;

    red[c] = t;
    __syncthreads();
    for (int s = 128; s > 0; s >>= 1) {
        if (c < s) red[c] += red[c + s];
        __syncthreads();
    }
    d_t[b*COUT + c] = t * ((float)COUT / red[0]);
}

// ---------------------------------------------------------------------------
// Main: persistent fp16 implicit GEMM (R15 verbatim — frozen).
// ---------------------------------------------------------------------------
#define SM_A    0
#define SM_B    49152
#define SM_INV  98304
#define SM_ADD  99328
#define SM_TILE 100352
#define SMEM_SZ 100384

__device__ __forceinline__ uint32_t smem_u32(const void* p) {
    uint32_t a;
    asm("{ .reg .u64 t; cvta.to.shared.u64 t, %1; cvt.u32.u64 %0, t; }" : "=r"(a) : "l"(p));
    return a;
}
__device__ __forceinline__ void ldmx4(uint32_t* r, uint32_t addr) {
    asm volatile("ldmatrix.sync.aligned.m8n8.x4.shared.b16 {%0,%1,%2,%3}, [%4];"
        : "=r"(r[0]), "=r"(r[1]), "=r"(r[2]), "=r"(r[3]) : "r"(addr));
}
__device__ __forceinline__ void ldmx4t(uint32_t* r, uint32_t addr) {
    asm volatile("ldmatrix.sync.aligned.m8n8.x4.trans.shared.b16 {%0,%1,%2,%3}, [%4];"
        : "=r"(r[0]), "=r"(r[1]), "=r"(r[2]), "=r"(r[3]) : "r"(addr));
}
__device__ __forceinline__ void mma16816(float* c, const uint32_t* a, const uint32_t* b) {
    asm volatile(
        "mma.sync.aligned.m16n8k16.row.col.f32.f16.f16.f32 "
        "{%0,%1,%2,%3}, {%4,%5,%6,%7}, {%8,%9}, {%0,%1,%2,%3};"
        : "+f"(c[0]), "+f"(c[1]), "+f"(c[2]), "+f"(c[3])
        : "r"(a[0]), "r"(a[1]), "r"(a[2]), "r"(a[3]), "r"(b[0]), "r"(b[1]));
}
__device__ __forceinline__ uint32_t sw128(uint32_t off) {
    return off ^ ((off >> 3) & 0x70);
}
__device__ __forceinline__ uint32_t swzA(uint32_t off) {
    return off ^ (((off >> 8) & 7) << 4);
}
__device__ __forceinline__ void cp16(uint32_t saddr, const void* g) {
    asm volatile("cp.async.cg.shared.global [%0], [%1], 16;" :: "r"(saddr), "l"(g) : "memory");
}
__device__ __forceinline__ void cp4(uint32_t saddr, const void* g) {
    asm volatile("cp.async.ca.shared.global [%0], [%1], 4;" :: "r"(saddr), "l"(g) : "memory");
}
#define CP_COMMIT() asm volatile("cp.async.commit_group;" ::: "memory")
#define CP_WAIT1()  asm volatile("cp.async.wait_group 1;" ::: "memory")
#define CP_WAIT0()  asm volatile("cp.async.wait_group 0;" ::: "memory")

__device__ __forceinline__ void issueA(uint32_t su, int t, unsigned tileid,
                                       int cc, int stg) {
    int rs = cc >> 2, cb = cc & 3;
    int dh = rs / 3, dw = rs - dh*3;
    int bb = (int)(tileid / TPB);
    int tl = (int)(tileid - bb*TPB);
    const __half* base = (dw == 1) ? d_xq : d_xp;
    int rowhalf = tl*128 + dh*64 + ((dw == 2) ? 2 : 0);
    const char* src0 = (const char*)(base + ((size_t)bb*CIN + cb*64) * SLAB64)
                       + (size_t)rowhalf * 2;
    uint32_t dstA = su + SM_A + stg*16384;
    if (dw != 2) {
        #pragma unroll
        for (int q = 0; q < 4; q++) {
            int u = q*256 + t;
            int ci = u >> 4, s = u & 15;
            cp16(dstA + swzA((uint32_t)(ci*256 + s*16)),
                 src0 + (size_t)ci*(SLAB64*2) + s*16);
        }
    } else {
        #pragma unroll
        for (int q = 0; q < 16; q++) {
            int u = q*256 + t;
            int ci = u >> 6, w4 = u & 63;
            cp4(dstA + swzA((uint32_t)(ci*256 + w4*4)),
                src0 + (size_t)ci*(SLAB64*2) + w4*4);
        }
    }
}

__global__ void __launch_bounds__(256, 2)
conv_mma_kernel(const float* __restrict__ gamma, const float* __restrict__ beta,
                const float* __restrict__ mean,  const float* __restrict__ var,
                float* __restrict__ out)
{
    extern __shared__ __align__(1024) char smem[];
    float* inv_s = (float*)(smem + SM_INV);
    float* add_s = (float*)(smem + SM_ADD);
    volatile unsigned int* tile_s = (volatile unsigned int*)(smem + SM_TILE);
    const uint32_t su = smem_u32(smem);

    const int t = threadIdx.x;
    const int lane = t & 31;
    const int wrp = t >> 5;
    const int wm = (wrp & 1) * 64;
    const int wn = (wrp >> 1) * 32;
    const int nh = blockIdx.x & 1;

    {
        float iv = gamma[t] * rsqrtf(var[t] + 1e-5f);
        inv_s[t] = iv;
        add_s[t] = beta[t] - mean[t]*iv;
    }

    const int a_i  = lane & 7;
    const int a_kh = (lane >> 4) & 1;
    const int a_m8 = ((lane >> 3) & 1) * 8;
    const int b_row = ((lane & 16) ? 8 : 0) + (lane & 7);
    const int b_kb  = (lane & 8) ? 16 : 0;

    const char* bsrc = (const char*)d_bimg + (size_t)nh * 16384;

    if (t == 0) tile_s[0] = atomicAdd(&d_ctr[nh], 1u);
    __syncthreads();
    unsigned tile = tile_s[0];

    if (tile < NTILE) {
        #pragma unroll
        for (int pc = 0; pc < 2; pc++) {
            const char* bs = bsrc + (size_t)pc * BTILE;
            uint32_t bdst = su + SM_B + pc*16384;
            #pragma unroll
            for (int q = 0; q < 4; q++)
                cp16(bdst + (uint32_t)(q*256 + t)*16, bs + (q*256 + t)*16);
            issueA(su, t, tile, pc, pc);
            CP_COMMIT();
        }
        CP_WAIT1();
        __syncthreads();

        for (;;) {
            const int bb = (int)(tile / TPB);
            const int tl = (int)(tile - bb*TPB);

            float acc[4][4][4];
            #pragma unroll
            for (int i = 0; i < 4; i++)
                #pragma unroll
                for (int j = 0; j < 4; j++)
                    #pragma unroll
                    for (int q = 0; q < 4; q++) acc[i][j][q] = 0.f;

            uint32_t afb[2][4][4];
            uint32_t bfb[2][4][2];

            for (int c = 0; c < NIMG; c++) {
                if (c == 0 && t == 0) tile_s[1] = atomicAdd(&d_ctr[nh], 1u);

                const int cc = c + 2;
                const int stg = cc % 3;
                {
                    int bcch = (cc >= NIMG) ? cc - NIMG : cc;
                    const char* bs = bsrc + (size_t)bcch * BTILE;
                    uint32_t bdst = su + SM_B + stg*16384;
                    #pragma unroll
                    for (int q = 0; q < 4; q++)
                        cp16(bdst + (uint32_t)(q*256 + t)*16, bs + (q*256 + t)*16);
                }
                if (cc < NIMG) {
                    issueA(su, t, tile, cc, stg);
                } else {
                    unsigned nt = tile_s[1];
                    if (nt < NTILE) issueA(su, t, nt, cc - NIMG, stg);
                }
                CP_COMMIT();

                const uint32_t Ast = su + SM_A + (c % 3)*16384;
                const uint32_t Bst = su + SM_B + (c % 3)*16384;

                #pragma unroll
                for (int am = 0; am < 4; am++) {
                    uint32_t ad = (uint32_t)((a_kh*8 + a_i)*256
                                           + (wm + am*16 + a_m8)*2);
                    ldmx4t(afb[0][am], Ast + swzA(ad));
                }
                #pragma unroll
                for (int bp = 0; bp < 2; bp++) {
                    uint32_t rr[4];
                    uint32_t off = (uint32_t)((wn + bp*16 + b_row)*128 + b_kb);
                    ldmx4(rr, Bst + sw128(off));
                    bfb[0][2*bp][0] = rr[0]; bfb[0][2*bp][1] = rr[1];
                    bfb[0][2*bp+1][0] = rr[2]; bfb[0][2*bp+1][1] = rr[3];
                }

                #pragma unroll
                for (int ks = 0; ks < 4; ks++) {
                    const int cur = ks & 1;
                    const int nxt = cur ^ 1;
                    if (ks < 3) {
                        #pragma unroll
                        for (int am = 0; am < 4; am++) {
                            uint32_t ad = (uint32_t)(((ks+1)*16 + a_kh*8 + a_i)*256
                                                   + (wm + am*16 + a_m8)*2);
                            ldmx4t(afb[nxt][am], Ast + swzA(ad));
                        }
                        #pragma unroll
                        for (int bp = 0; bp < 2; bp++) {
                            uint32_t rr[4];
                            uint32_t off = (uint32_t)((wn + bp*16 + b_row)*128
                                                    + (ks+1)*32 + b_kb);
                            ldmx4(rr, Bst + sw128(off));
                            bfb[nxt][2*bp][0] = rr[0]; bfb[nxt][2*bp][1] = rr[1];
                            bfb[nxt][2*bp+1][0] = rr[2]; bfb[nxt][2*bp+1][1] = rr[3];
                        }
                    }
                    #pragma unroll
                    for (int am = 0; am < 4; am++)
                        #pragma unroll
                        for (int bn = 0; bn < 4; bn++)
                            mma16816(acc[am][bn], afb[cur][am], bfb[cur][bn]);
                }

                CP_WAIT1();
                __syncthreads();
            }

            const float* tp = d_t + bb*COUT;
            #pragma unroll
            for (int am = 0; am < 4; am++) {
                int mr0 = tl*128 + wm + am*16 + (lane >> 2);
                #pragma unroll
                for (int half = 0; half < 2; half++) {
                    int mp = mr0 + half*8;
                    int h = mp >> 6;
                    int w = mp & 63;
                    bool valid = (w < Ws);
                    float* op = out + (size_t)bb*(COUT*HW) + h*Ws + w;
                    #pragma unroll
                    for (int bn = 0; bn < 4; bn++) {
                        int n = nh*128 + wn + bn*8 + 2*(lane & 3);
                        float v0 = fmaf(acc[am][bn][half*2+0], inv_s[n],   add_s[n]);
                        float v1 = fmaf(acc[am][bn][half*2+1], inv_s[n+1], add_s[n+1]);
                        v0 = fmaxf(v0, 0.f) * __ldg(tp + n);
                        v1 = fmaxf(v1, 0.f) * __ldg(tp + n + 1);
                        if (valid) {
                            op[(size_t)n * HW] = v0;
                            op[(size_t)(n+1) * HW] = v1;
                        }
                    }
                }
            }

            unsigned nt = tile_s[1];
            __syncthreads();
            tile = nt;
            if (tile >= NTILE) break;
        }
    }
    CP_WAIT0();
}

// ---------------------------------------------------------------------------
extern "C" void kernel_launch(void* const* d_in, const int* in_sizes, int n_in,
                              void* d_out, int out_size) {
    const float* x     = (const float*)d_in[0];
    const float* cw    = (const float*)d_in[1];
    const float* gw    = (const float*)d_in[2];
    const float* gb    = (const float*)d_in[3];
    const float* gamma = (const float*)d_in[4];
    const float* beta  = (const float*)d_in[5];
    const float* mean  = (const float*)d_in[6];
    const float* var   = (const float*)d_in[7];
    float* out = (float*)d_out;

    static bool attr_set = false;
    if (!attr_set) {
        cudaFuncSetAttribute(conv_mma_kernel,
                             cudaFuncAttributeMaxDynamicSharedMemorySize, SMEM_SZ);
        attr_set = true;
    }

    prep_x_kernel<<<B_*CIN, 256>>>(x);
    gate_w_kernel<<<B_ + NIMG, 256>>>(gw, gb, cw);
    conv_mma_kernel<<<296, 256, SMEM_SZ>>>(gamma, beta, mean, var, out);
}